// round 6
// baseline (speedup 1.0000x reference)
#include <cuda_runtime.h>
#include <cuda_bf16.h>
#include <math.h>
#include <stdint.h>

#define KK 128
#define DD 64
#define BM 128
#define LOG2PI 1.8378770664093454835
#define NT 256

#define RSTRIDE 272             // bytes per image row (136 halves; /4 = 68 ≡ 4 mod 32)
#define IMG     34816           // 128 * 272
#define SM_B    0               // 3 weight-split images
#define SM_A    (3 * IMG)       // 3 x-split images
#define SM_MH   (6 * IMG)       // mh[128][2] floats
#define SM_SH   (SM_MH + 1024)  // sh[128][2] floats
#define SM_SA   (SM_SH + 1024)  // A_k floats
#define SM_DLL  (SM_SA + 512)   // 8 doubles
#define SM_TOTAL (SM_DLL + 64)

typedef unsigned int u32t;
typedef unsigned long long u64t;

static __device__ __align__(16) unsigned short g_Bimg[3][KK * 136];
__device__ float  g_A[KK];
__device__ double g_kl;
__device__ double g_ll;
__device__ unsigned g_cnt;
__device__ double g_estick[KK], g_e1m[KK], g_base[KK], g_klk[KK];

// ---------------------------------------------------------------- ptx helpers
#define LDSM4(r0, r1, r2, r3, a) \
    asm volatile("ldmatrix.sync.aligned.m8n8.x4.shared.b16 {%0,%1,%2,%3}, [%4];" \
        : "=r"(r0), "=r"(r1), "=r"(r2), "=r"(r3) : "r"(a))

#define MMA16816(c, a0, a1, a2, a3, b0, b1) \
    asm volatile("mma.sync.aligned.m16n8k16.row.col.f32.bf16.bf16.f32 " \
        "{%0,%1,%2,%3}, {%4,%5,%6,%7}, {%8,%9}, {%0,%1,%2,%3};" \
        : "+f"((c).x), "+f"((c).y), "+f"((c).z), "+f"((c).w) \
        : "r"(a0), "r"(a1), "r"(a2), "r"(a3), "r"(b0), "r"(b1))

__device__ __forceinline__ u32t smem_u32(const void* p) {
    u32t a;
    asm("{ .reg .u64 t; cvta.to.shared.u64 t, %1; cvt.u32.u64 %0, t; }"
        : "=r"(a) : "l"(p));
    return a;
}

__device__ __forceinline__ void split3(float v, unsigned short& h,
                                       unsigned short& m, unsigned short& l) {
    __nv_bfloat16 b0 = __float2bfloat16(v);
    float r1 = v - __bfloat162float(b0);
    __nv_bfloat16 b1 = __float2bfloat16(r1);
    float r2 = r1 - __bfloat162float(b1);
    __nv_bfloat16 b2 = __float2bfloat16(r2);
    h = __bfloat16_as_ushort(b0);
    m = __bfloat16_as_ushort(b1);
    l = __bfloat16_as_ushort(b2);
}

__device__ float dgf(float x) {    // digamma, float
    float s = 0.0f;
    while (x < 8.0f) { s -= 1.0f / x; x += 1.0f; }
    float inv = 1.0f / x, i2 = inv * inv;
    float r = logf(x) - 0.5f * inv
        - i2 * (8.3333333e-2f - i2 * (8.3333333e-3f - i2 * (3.9682540e-3f
          - i2 * (4.1666667e-3f - i2 * 7.5757576e-3f))));
    return r + s;
}

// ---------------------------------------------------------------- setup, stage 1
__global__ void setup1_kernel(const float* __restrict__ nu, const float* __restrict__ nv,
                              const float* __restrict__ ntau, const float* __restrict__ nc,
                              const float* __restrict__ nn, const float* __restrict__ nB) {
    __shared__ double sred[3][2];
    int k = blockIdx.x, d = threadIdx.x;
    int lane = d & 31, warp = d >> 5;

    float c = nc[k];
    float n = nn[k] - (float)DD - 2.0f;

    float t   = ntau[k * DD + d] / c;
    float B   = nB[k * DD + d] - c * t * t;
    float nbv = n / B;
    float w2 = -0.5f * nbv;            // feature 2d (pairs with x^2)
    float w1 = t * nbv;                // feature 2d+1 (pairs with x)

    unsigned short h, m, l;
    int o = k * 136 + 2 * d;
    split3(w2, h, m, l);
    g_Bimg[0][o] = h; g_Bimg[1][o] = m; g_Bimg[2][o] = l;
    split3(w1, h, m, l);
    g_Bimg[0][o + 1] = h; g_Bimg[1][o + 1] = m; g_Bimg[2][o + 1] = l;

    double logb1 = (double)logf(0.5f * B);
    double t2nb  = (double)(t * t * nbv);
    double rat   = (double)((0.5f - 0.5f * B) / (0.5f * B));

    #pragma unroll
    for (int off = 16; off > 0; off >>= 1) {
        logb1 += __shfl_down_sync(0xffffffffu, logb1, off);
        t2nb  += __shfl_down_sync(0xffffffffu, t2nb,  off);
        rat   += __shfl_down_sync(0xffffffffu, rat,   off);
    }
    if (lane == 0) { sred[0][warp] = logb1; sred[1][warp] = t2nb; sred[2][warp] = rat; }
    __syncthreads();

    if (d == 0) {
        double SlogB = sred[0][0] + sred[0][1];
        double St2   = sred[1][0] + sred[1][1];
        double Srat  = sred[2][0] + sred[2][1];

        float  a1f = 0.5f * n;
        double a1 = (double)a1f, a0g = 0.5 * ((double)DD + 2.0), b0g = 0.5;
        double dga1 = (double)dgf(a1f);
        double lga1 = (double)lgammaf(a1f);
        double lga0g = (double)lgammaf((float)a0g);

        double e_log_det = (double)DD * dga1 - SlogB;
        double klg = (double)DD * ((a1 - a0g) * dga1 - lga1 + lga0g - a0g * log(b0g))
                   + a0g * SlogB + a1 * Srat;
        double kln = 0.5 * ((double)DD * ((double)logf(c) + 1.0 / (double)c - 1.0) + St2);

        float u = nu[k] + 1.0f, v = nv[k] + 1.0f;
        double dgu = (double)dgf(u), dgv = (double)dgf(v), dguv = (double)dgf(u + v);
        double klb = (double)lgammaf(u + v) - (double)lgammaf(u) - (double)lgammaf(v)
                   + ((double)u - 1.0) * dgu + ((double)v - 1.0) * dgv
                   + (2.0 - (double)u - (double)v) * dguv;

        g_estick[k] = dgu - dguv;
        g_e1m[k]    = dgv - dguv;
        g_base[k]   = 0.5 * (e_log_det - (double)DD * LOG2PI - St2
                             - (double)DD / (double)c);
        g_klk[k]    = klb + klg + kln;
    }
}

// ---------------------------------------------------------------- setup, stage 2
__global__ void setup2_kernel() {
    __shared__ double sh[KK], pre[KK], red[KK];
    int k = threadIdx.x;
    sh[k]  = g_e1m[k];
    red[k] = g_klk[k];
    __syncthreads();
    if (k == 0) {
        double a = 0.0;
        for (int j = 0; j < KK; j++) { pre[j] = a; a += sh[j]; }
    }
    __syncthreads();
    g_A[k] = (float)(g_estick[k] + pre[k] + g_base[k]);
    __syncthreads();
    for (int off = KK / 2; off > 0; off >>= 1) {
        if (k < off) red[k] += red[k + off];
        __syncthreads();
    }
    if (k == 0) { g_kl = red[0]; g_ll = 0.0; g_cnt = 0; }
}

// ---------------------------------------------------------------- main: mma.sync GEMM + softmax
__global__ void __launch_bounds__(NT, 1)
main_kernel(const float* __restrict__ x, float* __restrict__ out, int ntiles,
            long long outidx) {
    extern __shared__ char smem[];
    u32t sbase = smem_u32(smem);
    float*  mh  = (float*)(smem + SM_MH);
    float*  shm = (float*)(smem + SM_SH);
    float*  sAk = (float*)(smem + SM_SA);
    double* dll = (double*)(smem + SM_DLL);

    int tid = threadIdx.x;
    int w = tid >> 5, L = tid & 31;
    int mw = w & 3, nw = w >> 2;           // warp tile: rows mw*32..+31, cols nw*64..+63
    int g = L >> 2, tig = L & 3;

    // stage constant B images + A_k
    {
        const float4* src = (const float4*)g_Bimg;
        float4* dst = (float4*)smem;
        for (int i = tid; i < 6528; i += NT) dst[i] = src[i];
    }
    if (tid < KK) sAk[tid] = g_A[tid];
    __syncthreads();

    float ak[8][2];
    #pragma unroll
    for (int nj = 0; nj < 8; nj++) {
        ak[nj][0] = sAk[nw * 64 + nj * 8 + tig * 2];
        ak[nj][1] = sAk[nw * 64 + nj * 8 + tig * 2 + 1];
    }

    const u32t lane_off = (u32t)((L & 15) * RSTRIDE + ((L >> 4) & 1) * 16);
    const u32t abase = sbase + SM_A + (u32t)(mw * 32) * RSTRIDE + lane_off;
    const u32t bbase = sbase + SM_B + (u32t)(nw * 64) * RSTRIDE + lane_off;

    const int PA[6] = {0, 0, 1, 1, 0, 2};
    const int PB[6] = {0, 1, 0, 1, 2, 0};

    int srow = tid >> 1;                   // staging: this thread's x row
    int d0 = (tid & 1) * 32;               // and 32-dim half
    u32t* i0 = (u32t*)(smem + SM_A)           + srow * 68;
    u32t* i1 = (u32t*)(smem + SM_A + IMG)     + srow * 68;
    u32t* i2 = (u32t*)(smem + SM_A + 2 * IMG) + srow * 68;

    double llacc = 0.0;

    for (int tile = blockIdx.x; tile < ntiles; tile += gridDim.x) {
        int rowbase = tile * BM;

        // ---- stage A: split x into 3 bf16 images of (x^2, x) features
        {
            const float4* xp = (const float4*)(x + (size_t)(rowbase + srow) * DD + d0);
            #pragma unroll
            for (int q = 0; q < 8; q++) {
                float4 v = xp[q];
                float xs[4] = {v.x, v.y, v.z, v.w};
                u32t H[4], M[4], Lo[4];
                #pragma unroll
                for (int i = 0; i < 4; i++) {
                    unsigned short h2, m2, l2, h1, m1, l1;
                    split3(xs[i] * xs[i], h2, m2, l2);
                    split3(xs[i], h1, m1, l1);
                    H[i]  = (u32t)h2 | ((u32t)h1 << 16);
                    M[i]  = (u32t)m2 | ((u32t)m1 << 16);
                    Lo[i] = (u32t)l2 | ((u32t)l1 << 16);
                }
                int d = d0 + q * 4;
                ((u64t*)(i0 + d))[0] = (u64t)H[0]  | ((u64t)H[1]  << 32);
                ((u64t*)(i0 + d))[1] = (u64t)H[2]  | ((u64t)H[3]  << 32);
                ((u64t*)(i1 + d))[0] = (u64t)M[0]  | ((u64t)M[1]  << 32);
                ((u64t*)(i1 + d))[1] = (u64t)M[2]  | ((u64t)M[3]  << 32);
                ((u64t*)(i2 + d))[0] = (u64t)Lo[0] | ((u64t)Lo[1] << 32);
                ((u64t*)(i2 + d))[1] = (u64t)Lo[2] | ((u64t)Lo[3] << 32);
            }
        }
        __syncthreads();

        // ---- 48-chunk mma loop (6 split products x 8 k16 chunks)
        float4 acc[2][8];
        #pragma unroll
        for (int mi = 0; mi < 2; mi++)
            #pragma unroll
            for (int nj = 0; nj < 8; nj++)
                acc[mi][nj] = make_float4(0.f, 0.f, 0.f, 0.f);

        #pragma unroll
        for (int p = 0; p < 6; p++) {
            u32t aB = abase + (u32t)PA[p] * IMG;
            u32t bB = bbase + (u32t)PB[p] * IMG;
            #pragma unroll
            for (int s = 0; s < 8; s++) {
                u32t A0[4], A1[4], B[4][4];
                LDSM4(A0[0], A0[1], A0[2], A0[3], aB + s * 32);
                LDSM4(A1[0], A1[1], A1[2], A1[3], aB + 16 * RSTRIDE + s * 32);
                #pragma unroll
                for (int pr = 0; pr < 4; pr++)
                    LDSM4(B[pr][0], B[pr][1], B[pr][2], B[pr][3],
                          bB + pr * 16 * RSTRIDE + s * 32);
                #pragma unroll
                for (int nj = 0; nj < 8; nj++) {
                    u32t b0 = B[nj >> 1][nj & 1];
                    u32t b1 = B[nj >> 1][2 + (nj & 1)];
                    MMA16816(acc[0][nj], A0[0], A0[1], A0[2], A0[3], b0, b1);
                    MMA16816(acc[1][nj], A1[0], A1[1], A1[2], A1[3], b0, b1);
                }
            }
        }

        // ---- softmax epilogue
        float vmax[2][2] = {{-3.4e38f, -3.4e38f}, {-3.4e38f, -3.4e38f}};
        #pragma unroll
        for (int mi = 0; mi < 2; mi++)
            #pragma unroll
            for (int nj = 0; nj < 8; nj++) {
                acc[mi][nj].x += ak[nj][0];
                acc[mi][nj].y += ak[nj][1];
                acc[mi][nj].z += ak[nj][0];
                acc[mi][nj].w += ak[nj][1];
                vmax[mi][0] = fmaxf(vmax[mi][0], fmaxf(acc[mi][nj].x, acc[mi][nj].y));
                vmax[mi][1] = fmaxf(vmax[mi][1], fmaxf(acc[mi][nj].z, acc[mi][nj].w));
            }
        #pragma unroll
        for (int mi = 0; mi < 2; mi++)
            #pragma unroll
            for (int rh = 0; rh < 2; rh++) {
                float v = vmax[mi][rh];
                v = fmaxf(v, __shfl_xor_sync(0xffffffffu, v, 1));
                v = fmaxf(v, __shfl_xor_sync(0xffffffffu, v, 2));
                vmax[mi][rh] = v;
            }
        if (tig == 0) {
            #pragma unroll
            for (int mi = 0; mi < 2; mi++)
                #pragma unroll
                for (int rh = 0; rh < 2; rh++)
                    mh[(mw * 32 + mi * 16 + g + rh * 8) * 2 + nw] = vmax[mi][rh];
        }
        __syncthreads();

        float Mx[2][2], vs[2][2] = {{0.f, 0.f}, {0.f, 0.f}};
        #pragma unroll
        for (int mi = 0; mi < 2; mi++)
            #pragma unroll
            for (int rh = 0; rh < 2; rh++) {
                int r = (mw * 32 + mi * 16 + g + rh * 8) * 2;
                Mx[mi][rh] = fmaxf(mh[r], mh[r + 1]);
            }
        #pragma unroll
        for (int mi = 0; mi < 2; mi++)
            #pragma unroll
            for (int nj = 0; nj < 8; nj++) {
                acc[mi][nj].x = __expf(acc[mi][nj].x - Mx[mi][0]);
                acc[mi][nj].y = __expf(acc[mi][nj].y - Mx[mi][0]);
                acc[mi][nj].z = __expf(acc[mi][nj].z - Mx[mi][1]);
                acc[mi][nj].w = __expf(acc[mi][nj].w - Mx[mi][1]);
                vs[mi][0] += acc[mi][nj].x + acc[mi][nj].y;
                vs[mi][1] += acc[mi][nj].z + acc[mi][nj].w;
            }
        #pragma unroll
        for (int mi = 0; mi < 2; mi++)
            #pragma unroll
            for (int rh = 0; rh < 2; rh++) {
                float v = vs[mi][rh];
                v += __shfl_xor_sync(0xffffffffu, v, 1);
                v += __shfl_xor_sync(0xffffffffu, v, 2);
                vs[mi][rh] = v;
            }
        if (tig == 0) {
            #pragma unroll
            for (int mi = 0; mi < 2; mi++)
                #pragma unroll
                for (int rh = 0; rh < 2; rh++)
                    shm[(mw * 32 + mi * 16 + g + rh * 8) * 2 + nw] = vs[mi][rh];
        }
        __syncthreads();

        float inv[2][2];
        #pragma unroll
        for (int mi = 0; mi < 2; mi++)
            #pragma unroll
            for (int rh = 0; rh < 2; rh++) {
                int r = (mw * 32 + mi * 16 + g + rh * 8) * 2;
                float S = shm[r] + shm[r + 1];
                inv[mi][rh] = 1.0f / S;
                if (nw == 0 && tig == 0)
                    llacc += (double)(Mx[mi][rh] + __logf(S));
            }
        #pragma unroll
        for (int mi = 0; mi < 2; mi++) {
            int r0 = rowbase + mw * 32 + mi * 16 + g;
            #pragma unroll
            for (int nj = 0; nj < 8; nj++) {
                int col = nw * 64 + nj * 8 + tig * 2;
                float2 v0 = make_float2(acc[mi][nj].x * inv[mi][0],
                                        acc[mi][nj].y * inv[mi][0]);
                float2 v1 = make_float2(acc[mi][nj].z * inv[mi][1],
                                        acc[mi][nj].w * inv[mi][1]);
                *(float2*)(out + (size_t)r0 * KK + col) = v0;
                *(float2*)(out + (size_t)(r0 + 8) * KK + col) = v1;
            }
        }
    }

    // ---- ll reduction + finalize
    #pragma unroll
    for (int off = 16; off > 0; off >>= 1)
        llacc += __shfl_xor_sync(0xffffffffu, llacc, off);
    if (L == 0) dll[w] = llacc;
    __syncthreads();
    if (tid == 0) {
        double t = 0.0;
        #pragma unroll
        for (int i = 0; i < 8; i++) t += dll[i];
        atomicAdd(&g_ll, t);
        __threadfence();
        unsigned old = atomicAdd(&g_cnt, 1u);
        if (old == gridDim.x - 1) {
            __threadfence();
            double ll = *((volatile double*)&g_ll);
            out[outidx] = (float)(g_kl - ll);
        }
    }
}

// ---------------------------------------------------------------- launch
extern "C" void kernel_launch(void* const* d_in, const int* in_sizes, int n_in,
                              void* d_out, int out_size) {
    const float* x    = (const float*)d_in[0];
    const float* nu   = (const float*)d_in[1];
    const float* nv   = (const float*)d_in[2];
    const float* ntau = (const float*)d_in[3];
    const float* nc   = (const float*)d_in[4];
    const float* nn   = (const float*)d_in[5];
    const float* nB   = (const float*)d_in[6];

    int K = in_sizes[1];
    int D = in_sizes[3] / K;
    int N = in_sizes[0] / D;
    int ntiles = N / BM;
    int grid = ntiles < 148 ? ntiles : 148;

    cudaFuncSetAttribute(main_kernel, cudaFuncAttributeMaxDynamicSharedMemorySize,
                         SM_TOTAL);

    setup1_kernel<<<KK, DD>>>(nu, nv, ntau, nc, nn, nB);
    setup2_kernel<<<1, KK>>>();
    main_kernel<<<grid, NT, SM_TOTAL>>>(x, (float*)d_out, ntiles,
                                        (long long)out_size - 1);
}

// round 7
// speedup vs baseline: 1.0003x; 1.0003x over previous
#include <cuda_runtime.h>
#include <cuda_bf16.h>
#include <math.h>
#include <stdint.h>

#define KK 128
#define DD 64
#define BM 128
#define LOG2PI 1.8378770664093454835
#define NT 256

#define RSTRIDE 272             // bytes per image row (136 halves; /4 = 68 ≡ 4 mod 32)
#define IMG     34816           // 128 * 272
#define SM_B    0               // 3 weight-split images
#define SM_A    (3 * IMG)       // 3 x-split images
#define SM_MH   (6 * IMG)       // mh[128][2] floats
#define SM_SH   (SM_MH + 1024)  // sh[128][2] floats
#define SM_SA   (SM_SH + 1024)  // A_k floats
#define SM_DLL  (SM_SA + 512)   // 8 doubles
#define SM_TOTAL (SM_DLL + 64)

typedef unsigned int u32t;
typedef unsigned long long u64t;

static __device__ __align__(16) unsigned short g_Bimg[3][KK * 136];
__device__ float  g_A[KK];
__device__ double g_kl;
__device__ double g_ll;
__device__ unsigned g_cnt;
__device__ double g_estick[KK], g_e1m[KK], g_base[KK], g_klk[KK];

// ---------------------------------------------------------------- ptx helpers
#define LDSM4(r0, r1, r2, r3, a) \
    asm volatile("ldmatrix.sync.aligned.m8n8.x4.shared.b16 {%0,%1,%2,%3}, [%4];" \
        : "=r"(r0), "=r"(r1), "=r"(r2), "=r"(r3) : "r"(a))

#define MMA16816(c, a0, a1, a2, a3, b0, b1) \
    asm volatile("mma.sync.aligned.m16n8k16.row.col.f32.bf16.bf16.f32 " \
        "{%0,%1,%2,%3}, {%4,%5,%6,%7}, {%8,%9}, {%0,%1,%2,%3};" \
        : "+f"((c).x), "+f"((c).y), "+f"((c).z), "+f"((c).w) \
        : "r"(a0), "r"(a1), "r"(a2), "r"(a3), "r"(b0), "r"(b1))

__device__ __forceinline__ u32t smem_u32(const void* p) {
    u32t a;
    asm("{ .reg .u64 t; cvta.to.shared.u64 t, %1; cvt.u32.u64 %0, t; }"
        : "=r"(a) : "l"(p));
    return a;
}

__device__ __forceinline__ void split3(float v, unsigned short& h,
                                       unsigned short& m, unsigned short& l) {
    __nv_bfloat16 b0 = __float2bfloat16(v);
    float r1 = v - __bfloat162float(b0);
    __nv_bfloat16 b1 = __float2bfloat16(r1);
    float r2 = r1 - __bfloat162float(b1);
    __nv_bfloat16 b2 = __float2bfloat16(r2);
    h = __bfloat16_as_ushort(b0);
    m = __bfloat16_as_ushort(b1);
    l = __bfloat16_as_ushort(b2);
}

__device__ float dgf(float x) {    // digamma, float
    float s = 0.0f;
    while (x < 8.0f) { s -= 1.0f / x; x += 1.0f; }
    float inv = 1.0f / x, i2 = inv * inv;
    float r = logf(x) - 0.5f * inv
        - i2 * (8.3333333e-2f - i2 * (8.3333333e-3f - i2 * (3.9682540e-3f
          - i2 * (4.1666667e-3f - i2 * 7.5757576e-3f))));
    return r + s;
}

// ---------------------------------------------------------------- setup, stage 1
__global__ void setup1_kernel(const float* __restrict__ nu, const float* __restrict__ nv,
                              const float* __restrict__ ntau, const float* __restrict__ nc,
                              const float* __restrict__ nn, const float* __restrict__ nB) {
    __shared__ double sred[3][2];
    int k = blockIdx.x, d = threadIdx.x;
    int lane = d & 31, warp = d >> 5;

    float c = nc[k];
    float n = nn[k] - (float)DD - 2.0f;

    float t   = ntau[k * DD + d] / c;
    float B   = nB[k * DD + d] - c * t * t;
    float nbv = n / B;
    float w2 = -0.5f * nbv;            // feature 2d (pairs with x^2)
    float w1 = t * nbv;                // feature 2d+1 (pairs with x)

    unsigned short h, m, l;
    int o = k * 136 + 2 * d;
    split3(w2, h, m, l);
    g_Bimg[0][o] = h; g_Bimg[1][o] = m; g_Bimg[2][o] = l;
    split3(w1, h, m, l);
    g_Bimg[0][o + 1] = h; g_Bimg[1][o + 1] = m; g_Bimg[2][o + 1] = l;

    double logb1 = (double)logf(0.5f * B);
    double t2nb  = (double)(t * t * nbv);
    double rat   = (double)((0.5f - 0.5f * B) / (0.5f * B));

    #pragma unroll
    for (int off = 16; off > 0; off >>= 1) {
        logb1 += __shfl_down_sync(0xffffffffu, logb1, off);
        t2nb  += __shfl_down_sync(0xffffffffu, t2nb,  off);
        rat   += __shfl_down_sync(0xffffffffu, rat,   off);
    }
    if (lane == 0) { sred[0][warp] = logb1; sred[1][warp] = t2nb; sred[2][warp] = rat; }
    __syncthreads();

    if (d == 0) {
        double SlogB = sred[0][0] + sred[0][1];
        double St2   = sred[1][0] + sred[1][1];
        double Srat  = sred[2][0] + sred[2][1];

        float  a1f = 0.5f * n;
        double a1 = (double)a1f, a0g = 0.5 * ((double)DD + 2.0), b0g = 0.5;
        double dga1 = (double)dgf(a1f);
        double lga1 = (double)lgammaf(a1f);
        double lga0g = (double)lgammaf((float)a0g);

        double e_log_det = (double)DD * dga1 - SlogB;
        double klg = (double)DD * ((a1 - a0g) * dga1 - lga1 + lga0g - a0g * log(b0g))
                   + a0g * SlogB + a1 * Srat;
        double kln = 0.5 * ((double)DD * ((double)logf(c) + 1.0 / (double)c - 1.0) + St2);

        float u = nu[k] + 1.0f, v = nv[k] + 1.0f;
        double dgu = (double)dgf(u), dgv = (double)dgf(v), dguv = (double)dgf(u + v);
        double klb = (double)lgammaf(u + v) - (double)lgammaf(u) - (double)lgammaf(v)
                   + ((double)u - 1.0) * dgu + ((double)v - 1.0) * dgv
                   + (2.0 - (double)u - (double)v) * dguv;

        g_estick[k] = dgu - dguv;
        g_e1m[k]    = dgv - dguv;
        g_base[k]   = 0.5 * (e_log_det - (double)DD * LOG2PI - St2
                             - (double)DD / (double)c);
        g_klk[k]    = klb + klg + kln;
    }
}

// ---------------------------------------------------------------- setup, stage 2
__global__ void setup2_kernel() {
    __shared__ double sh[KK], pre[KK], red[KK];
    int k = threadIdx.x;
    sh[k]  = g_e1m[k];
    red[k] = g_klk[k];
    __syncthreads();
    if (k == 0) {
        double a = 0.0;
        for (int j = 0; j < KK; j++) { pre[j] = a; a += sh[j]; }
    }
    __syncthreads();
    g_A[k] = (float)(g_estick[k] + pre[k] + g_base[k]);
    __syncthreads();
    for (int off = KK / 2; off > 0; off >>= 1) {
        if (k < off) red[k] += red[k + off];
        __syncthreads();
    }
    if (k == 0) { g_kl = red[0]; g_ll = 0.0; g_cnt = 0; }
}

// ---------------------------------------------------------------- main: mma.sync GEMM + softmax
__global__ void __launch_bounds__(NT, 1)
main_kernel(const float* __restrict__ x, float* __restrict__ out, int ntiles,
            long long outidx) {
    extern __shared__ char smem[];
    u32t sbase = smem_u32(smem);
    float*  mh  = (float*)(smem + SM_MH);
    float*  shm = (float*)(smem + SM_SH);
    float*  sAk = (float*)(smem + SM_SA);
    double* dll = (double*)(smem + SM_DLL);

    int tid = threadIdx.x;
    int w = tid >> 5, L = tid & 31;
    int mw = w & 3, nw = w >> 2;           // warp tile: rows mw*32..+31, cols nw*64..+63
    int g = L >> 2, tig = L & 3;

    // stage constant B images + A_k
    {
        const float4* src = (const float4*)g_Bimg;
        float4* dst = (float4*)smem;
        for (int i = tid; i < 6528; i += NT) dst[i] = src[i];
    }
    if (tid < KK) sAk[tid] = g_A[tid];
    __syncthreads();

    float ak[8][2];
    #pragma unroll
    for (int nj = 0; nj < 8; nj++) {
        ak[nj][0] = sAk[nw * 64 + nj * 8 + tig * 2];
        ak[nj][1] = sAk[nw * 64 + nj * 8 + tig * 2 + 1];
    }

    const u32t lane_off = (u32t)((L & 15) * RSTRIDE + ((L >> 4) & 1) * 16);
    const u32t abase = sbase + SM_A + (u32t)(mw * 32) * RSTRIDE + lane_off;
    const u32t bbase = sbase + SM_B + (u32t)(nw * 64) * RSTRIDE + lane_off;

    const int PA[6] = {0, 0, 1, 1, 0, 2};
    const int PB[6] = {0, 1, 0, 1, 2, 0};

    int srow = tid >> 1;                   // staging: this thread's x row
    int d0 = (tid & 1) * 32;               // and 32-dim half
    u32t* i0 = (u32t*)(smem + SM_A)           + srow * 68;
    u32t* i1 = (u32t*)(smem + SM_A + IMG)     + srow * 68;
    u32t* i2 = (u32t*)(smem + SM_A + 2 * IMG) + srow * 68;

    double llacc = 0.0;

    for (int tile = blockIdx.x; tile < ntiles; tile += gridDim.x) {
        int rowbase = tile * BM;

        // ---- stage A: split x into 3 bf16 images of (x^2, x) features
        {
            const float4* xp = (const float4*)(x + (size_t)(rowbase + srow) * DD + d0);
            #pragma unroll
            for (int q = 0; q < 8; q++) {
                float4 v = xp[q];
                float xs[4] = {v.x, v.y, v.z, v.w};
                u32t H[4], M[4], Lo[4];
                #pragma unroll
                for (int i = 0; i < 4; i++) {
                    unsigned short h2, m2, l2, h1, m1, l1;
                    split3(xs[i] * xs[i], h2, m2, l2);
                    split3(xs[i], h1, m1, l1);
                    H[i]  = (u32t)h2 | ((u32t)h1 << 16);
                    M[i]  = (u32t)m2 | ((u32t)m1 << 16);
                    Lo[i] = (u32t)l2 | ((u32t)l1 << 16);
                }
                int d = d0 + q * 4;
                ((u64t*)(i0 + d))[0] = (u64t)H[0]  | ((u64t)H[1]  << 32);
                ((u64t*)(i0 + d))[1] = (u64t)H[2]  | ((u64t)H[3]  << 32);
                ((u64t*)(i1 + d))[0] = (u64t)M[0]  | ((u64t)M[1]  << 32);
                ((u64t*)(i1 + d))[1] = (u64t)M[2]  | ((u64t)M[3]  << 32);
                ((u64t*)(i2 + d))[0] = (u64t)Lo[0] | ((u64t)Lo[1] << 32);
                ((u64t*)(i2 + d))[1] = (u64t)Lo[2] | ((u64t)Lo[3] << 32);
            }
        }
        __syncthreads();

        // ---- 48-chunk mma loop (6 split products x 8 k16 chunks)
        float4 acc[2][8];
        #pragma unroll
        for (int mi = 0; mi < 2; mi++)
            #pragma unroll
            for (int nj = 0; nj < 8; nj++)
                acc[mi][nj] = make_float4(0.f, 0.f, 0.f, 0.f);

        #pragma unroll
        for (int p = 0; p < 6; p++) {
            u32t aB = abase + (u32t)PA[p] * IMG;
            u32t bB = bbase + (u32t)PB[p] * IMG;
            #pragma unroll
            for (int s = 0; s < 8; s++) {
                u32t A0[4], A1[4], B[4][4];
                LDSM4(A0[0], A0[1], A0[2], A0[3], aB + s * 32);
                LDSM4(A1[0], A1[1], A1[2], A1[3], aB + 16 * RSTRIDE + s * 32);
                #pragma unroll
                for (int pr = 0; pr < 4; pr++)
                    LDSM4(B[pr][0], B[pr][1], B[pr][2], B[pr][3],
                          bB + pr * 16 * RSTRIDE + s * 32);
                #pragma unroll
                for (int nj = 0; nj < 8; nj++) {
                    u32t b0 = B[nj >> 1][nj & 1];
                    u32t b1 = B[nj >> 1][2 + (nj & 1)];
                    MMA16816(acc[0][nj], A0[0], A0[1], A0[2], A0[3], b0, b1);
                    MMA16816(acc[1][nj], A1[0], A1[1], A1[2], A1[3], b0, b1);
                }
            }
        }

        // ---- softmax epilogue
        float vmax[2][2] = {{-3.4e38f, -3.4e38f}, {-3.4e38f, -3.4e38f}};
        #pragma unroll
        for (int mi = 0; mi < 2; mi++)
            #pragma unroll
            for (int nj = 0; nj < 8; nj++) {
                acc[mi][nj].x += ak[nj][0];
                acc[mi][nj].y += ak[nj][1];
                acc[mi][nj].z += ak[nj][0];
                acc[mi][nj].w += ak[nj][1];
                vmax[mi][0] = fmaxf(vmax[mi][0], fmaxf(acc[mi][nj].x, acc[mi][nj].y));
                vmax[mi][1] = fmaxf(vmax[mi][1], fmaxf(acc[mi][nj].z, acc[mi][nj].w));
            }
        #pragma unroll
        for (int mi = 0; mi < 2; mi++)
            #pragma unroll
            for (int rh = 0; rh < 2; rh++) {
                float v = vmax[mi][rh];
                v = fmaxf(v, __shfl_xor_sync(0xffffffffu, v, 1));
                v = fmaxf(v, __shfl_xor_sync(0xffffffffu, v, 2));
                vmax[mi][rh] = v;
            }
        if (tig == 0) {
            #pragma unroll
            for (int mi = 0; mi < 2; mi++)
                #pragma unroll
                for (int rh = 0; rh < 2; rh++)
                    mh[(mw * 32 + mi * 16 + g + rh * 8) * 2 + nw] = vmax[mi][rh];
        }
        __syncthreads();

        float Mx[2][2], vs[2][2] = {{0.f, 0.f}, {0.f, 0.f}};
        #pragma unroll
        for (int mi = 0; mi < 2; mi++)
            #pragma unroll
            for (int rh = 0; rh < 2; rh++) {
                int r = (mw * 32 + mi * 16 + g + rh * 8) * 2;
                Mx[mi][rh] = fmaxf(mh[r], mh[r + 1]);
            }
        #pragma unroll
        for (int mi = 0; mi < 2; mi++)
            #pragma unroll
            for (int nj = 0; nj < 8; nj++) {
                acc[mi][nj].x = __expf(acc[mi][nj].x - Mx[mi][0]);
                acc[mi][nj].y = __expf(acc[mi][nj].y - Mx[mi][0]);
                acc[mi][nj].z = __expf(acc[mi][nj].z - Mx[mi][1]);
                acc[mi][nj].w = __expf(acc[mi][nj].w - Mx[mi][1]);
                vs[mi][0] += acc[mi][nj].x + acc[mi][nj].y;
                vs[mi][1] += acc[mi][nj].z + acc[mi][nj].w;
            }
        #pragma unroll
        for (int mi = 0; mi < 2; mi++)
            #pragma unroll
            for (int rh = 0; rh < 2; rh++) {
                float v = vs[mi][rh];
                v += __shfl_xor_sync(0xffffffffu, v, 1);
                v += __shfl_xor_sync(0xffffffffu, v, 2);
                vs[mi][rh] = v;
            }
        if (tig == 0) {
            #pragma unroll
            for (int mi = 0; mi < 2; mi++)
                #pragma unroll
                for (int rh = 0; rh < 2; rh++)
                    shm[(mw * 32 + mi * 16 + g + rh * 8) * 2 + nw] = vs[mi][rh];
        }
        __syncthreads();

        float inv[2][2];
        #pragma unroll
        for (int mi = 0; mi < 2; mi++)
            #pragma unroll
            for (int rh = 0; rh < 2; rh++) {
                int r = (mw * 32 + mi * 16 + g + rh * 8) * 2;
                float S = shm[r] + shm[r + 1];
                inv[mi][rh] = 1.0f / S;
                if (nw == 0 && tig == 0)
                    llacc += (double)(Mx[mi][rh] + __logf(S));
            }
        #pragma unroll
        for (int mi = 0; mi < 2; mi++) {
            int r0 = rowbase + mw * 32 + mi * 16 + g;
            #pragma unroll
            for (int nj = 0; nj < 8; nj++) {
                int col = nw * 64 + nj * 8 + tig * 2;
                float2 v0 = make_float2(acc[mi][nj].x * inv[mi][0],
                                        acc[mi][nj].y * inv[mi][0]);
                float2 v1 = make_float2(acc[mi][nj].z * inv[mi][1],
                                        acc[mi][nj].w * inv[mi][1]);
                *(float2*)(out + (size_t)r0 * KK + col) = v0;
                *(float2*)(out + (size_t)(r0 + 8) * KK + col) = v1;
            }
        }
    }

    // ---- ll reduction + finalize
    #pragma unroll
    for (int off = 16; off > 0; off >>= 1)
        llacc += __shfl_xor_sync(0xffffffffu, llacc, off);
    if (L == 0) dll[w] = llacc;
    __syncthreads();
    if (tid == 0) {
        double t = 0.0;
        #pragma unroll
        for (int i = 0; i < 8; i++) t += dll[i];
        atomicAdd(&g_ll, t);
        __threadfence();
        unsigned old = atomicAdd(&g_cnt, 1u);
        if (old == gridDim.x - 1) {
            __threadfence();
            double ll = *((volatile double*)&g_ll);
            out[outidx] = (float)(g_kl - ll);
        }
    }
}

// ---------------------------------------------------------------- launch
extern "C" void kernel_launch(void* const* d_in, const int* in_sizes, int n_in,
                              void* d_out, int out_size) {
    const float* x    = (const float*)d_in[0];
    const float* nu   = (const float*)d_in[1];
    const float* nv   = (const float*)d_in[2];
    const float* ntau = (const float*)d_in[3];
    const float* nc   = (const float*)d_in[4];
    const float* nn   = (const float*)d_in[5];
    const float* nB   = (const float*)d_in[6];

    int K = in_sizes[1];
    int D = in_sizes[3] / K;
    int N = in_sizes[0] / D;
    int ntiles = N / BM;
    int grid = ntiles < 148 ? ntiles : 148;

    cudaFuncSetAttribute(main_kernel, cudaFuncAttributeMaxDynamicSharedMemorySize,
                         SM_TOTAL);

    setup1_kernel<<<KK, DD>>>(nu, nv, ntau, nc, nn, nB);
    setup2_kernel<<<1, KK>>>();
    main_kernel<<<grid, NT, SM_TOTAL>>>(x, (float*)d_out, ntiles,
                                        (long long)out_size - 1);
}